// round 4
// baseline (speedup 1.0000x reference)
#include <cuda_runtime.h>
#include <math.h>

// Problem constants (inner/dhead resolved at runtime from in_sizes)
#define BATCH   2
#define NTOK    2048
#define DIM     256
#define HEADS   8
#define TOK     (BATCH*NTOK)      // 4096
#define ATT_SCALE 0.125f          // DIM_HEAD=64 -> 64^-0.5
#define LN_EPS  1e-5f
#define INNER_MAX 16384           // DIM_HEAD * DIM = 64*256

// ---------------- scratch (static device globals; no cudaMalloc allowed) ----
__device__ float g_xn[TOK * DIM];                            //    4 MB
__device__ float g_q [(size_t)TOK * INNER_MAX];              //  256 MB
__device__ float g_k [(size_t)TOK * INNER_MAX];              //  256 MB
__device__ float g_v [(size_t)TOK * INNER_MAX];              //  256 MB
__device__ float g_s [(size_t)BATCH * HEADS * NTOK * NTOK];  //  256 MB
__device__ float g_o [(size_t)TOK * INNER_MAX];              //  256 MB

// ---------------- LayerNorm:  xn = (x-mu)*rsqrt(var+eps)*(gamma+1) ----------
__global__ void ln_kernel(const float* __restrict__ x,
                          const float* __restrict__ gamma,
                          float* __restrict__ xn)
{
    int row = blockIdx.x;            // one token per block, 256 threads
    int t   = threadIdx.x;
    float v = x[row * DIM + t];

    __shared__ float s1[8], s2[8];
    float a = v, b = v * v;
    #pragma unroll
    for (int o = 16; o > 0; o >>= 1) {
        a += __shfl_xor_sync(0xffffffffu, a, o);
        b += __shfl_xor_sync(0xffffffffu, b, o);
    }
    int lane = t & 31, w = t >> 5;
    if (lane == 0) { s1[w] = a; s2[w] = b; }
    __syncthreads();
    if (t == 0) {
        float sa = 0.f, sb = 0.f;
        #pragma unroll
        for (int i = 0; i < 8; i++) { sa += s1[i]; sb += s2[i]; }
        s1[0] = sa * (1.0f / DIM);
        s2[0] = sb * (1.0f / DIM);
    }
    __syncthreads();
    float mu  = s1[0];
    float var = s2[0] - mu * mu;
    float r   = rsqrtf(var + LN_EPS);
    xn[row * DIM + t] = (v - mu) * r * (gamma[t] + 1.0f);
}

// ---------------- tiled FP32 GEMM (128x128x16, 8x8 microtile) --------------
// C[m][n] = alpha * sum_k A[m][k] * B'[k][n]
//   BT=true :  B row-major (N,K) -> B'[k][n] = B[n*ldb + k]   (NT)
//   BT=false:  B row-major (K,N) -> B'[k][n] = B[k*ldb + n]   (NN)
// Batch z = zb*hdiv + zh with independent base strides.
// Requires M%128==0, N%128==0, K%16==0.
template<bool BT>
__global__ void __launch_bounds__(256, 2)
gemm_kernel(const float* __restrict__ A, const float* __restrict__ B,
            float* __restrict__ C,
            int K, int lda, int ldb, int ldc,
            int hdiv,
            long long sAb, long long sAh,
            long long sBb, long long sBh,
            long long sCb, long long sCh,
            float alpha)
{
    const int BK = 16;
    __shared__ float As[BK][128];
    __shared__ float Bs[BK][128];

    int bz = blockIdx.z;
    int zb = bz / hdiv, zh = bz % hdiv;
    const float* Ab = A + (long long)zb * sAb + (long long)zh * sAh;
    const float* Bb = B + (long long)zb * sBb + (long long)zh * sBh;
    float*       Cb = C + (long long)zb * sCb + (long long)zh * sCh;

    int m0 = blockIdx.y * 128;
    int n0 = blockIdx.x * 128;
    int tid = threadIdx.x;
    int tx = tid & 15;        // 0..15 -> 8 cols each
    int ty = tid >> 4;        // 0..15 -> 8 rows each

    float acc[8][8];
    #pragma unroll
    for (int i = 0; i < 8; i++)
        #pragma unroll
        for (int j = 0; j < 8; j++) acc[i][j] = 0.f;

    for (int k0 = 0; k0 < K; k0 += BK) {
        // A tile (128 x 16) transposed into As[k][m]
        {
            int r  = tid >> 2;           // 0..63
            int cg = (tid & 3) << 2;     // 0,4,8,12
            #pragma unroll
            for (int i = 0; i < 2; i++) {
                int row = r + i * 64;
                float4 a = *(const float4*)(Ab + (long long)(m0 + row) * lda + k0 + cg);
                As[cg + 0][row] = a.x;
                As[cg + 1][row] = a.y;
                As[cg + 2][row] = a.z;
                As[cg + 3][row] = a.w;
            }
        }
        // B tile into Bs[k][n]
        if (BT) {
            int r  = tid >> 2;
            int cg = (tid & 3) << 2;
            #pragma unroll
            for (int i = 0; i < 2; i++) {
                int row = r + i * 64;    // n index
                float4 b = *(const float4*)(Bb + (long long)(n0 + row) * ldb + k0 + cg);
                Bs[cg + 0][row] = b.x;
                Bs[cg + 1][row] = b.y;
                Bs[cg + 2][row] = b.z;
                Bs[cg + 3][row] = b.w;
            }
        } else {
            int kk = tid >> 5;           // 0..7
            int ng = (tid & 31) << 2;    // 0..124
            #pragma unroll
            for (int i = 0; i < 2; i++) {
                int krow = kk + i * 8;
                float4 b = *(const float4*)(Bb + (long long)(k0 + krow) * ldb + n0 + ng);
                *(float4*)&Bs[krow][ng] = b;
            }
        }
        __syncthreads();

        #pragma unroll
        for (int kk = 0; kk < BK; kk++) {
            float ra[8], rb[8];
            *(float4*)&ra[0] = *(const float4*)&As[kk][ty * 8];
            *(float4*)&ra[4] = *(const float4*)&As[kk][ty * 8 + 4];
            *(float4*)&rb[0] = *(const float4*)&Bs[kk][tx * 8];
            *(float4*)&rb[4] = *(const float4*)&Bs[kk][tx * 8 + 4];
            #pragma unroll
            for (int i = 0; i < 8; i++)
                #pragma unroll
                for (int j = 0; j < 8; j++)
                    acc[i][j] = fmaf(ra[i], rb[j], acc[i][j]);
        }
        __syncthreads();
    }

    #pragma unroll
    for (int i = 0; i < 8; i++) {
        long long row = m0 + ty * 8 + i;
        #pragma unroll
        for (int j = 0; j < 8; j += 4) {
            float4 c;
            c.x = acc[i][j + 0] * alpha;
            c.y = acc[i][j + 1] * alpha;
            c.z = acc[i][j + 2] * alpha;
            c.w = acc[i][j + 3] * alpha;
            *(float4*)(Cb + row * ldc + n0 + tx * 8 + j) = c;
        }
    }
}

// ---------------- row softmax over 2048 columns ---------------------------
__global__ void softmax_kernel(float* __restrict__ S)
{
    size_t row = blockIdx.x;
    float* sr = S + row * (size_t)NTOK;
    int t = threadIdx.x;                 // 256 threads, 8 elems each

    float v[8];
    float m = -1e30f;
    #pragma unroll
    for (int i = 0; i < 8; i++) {
        v[i] = sr[t + 256 * i];
        m = fmaxf(m, v[i]);
    }

    __shared__ float sred[8];
    float w = m;
    #pragma unroll
    for (int o = 16; o > 0; o >>= 1) w = fmaxf(w, __shfl_xor_sync(0xffffffffu, w, o));
    if ((t & 31) == 0) sred[t >> 5] = w;
    __syncthreads();
    if (t == 0) {
        float z = sred[0];
        #pragma unroll
        for (int i = 1; i < 8; i++) z = fmaxf(z, sred[i]);
        sred[0] = z;
    }
    __syncthreads();
    m = sred[0];
    __syncthreads();

    float sum = 0.f;
    #pragma unroll
    for (int i = 0; i < 8; i++) {
        v[i] = __expf(v[i] - m);
        sum += v[i];
    }
    float w2 = sum;
    #pragma unroll
    for (int o = 16; o > 0; o >>= 1) w2 += __shfl_xor_sync(0xffffffffu, w2, o);
    if ((t & 31) == 0) sred[t >> 5] = w2;
    __syncthreads();
    if (t == 0) {
        float z = 0.f;
        #pragma unroll
        for (int i = 0; i < 8; i++) z += sred[i];
        sred[0] = z;
    }
    __syncthreads();
    float inv = 1.0f / sred[0];

    #pragma unroll
    for (int i = 0; i < 8; i++) sr[t + 256 * i] = v[i] * inv;
}

// ---------------- launch ---------------------------------------------------
extern "C" void kernel_launch(void* const* d_in, const int* in_sizes, int n_in,
                              void* d_out, int out_size)
{
    // Insertion order (confirmed via R2/R3 bisection): x, gamma, Wq, Wk, Wv, Wo
    const float* x     = (const float*)d_in[0];
    const float* gamma = (const float*)d_in[1];
    const float* Wq    = (const float*)d_in[2];
    const float* Wk    = (const float*)d_in[3];
    const float* Wv    = (const float*)d_in[4];
    const float* Wo    = (const float*)d_in[5];
    float* out = (float*)d_out;

    // inner_dim derived from the actual Wq size: Wq is (inner, dim) row-major.
    // Reference code computes inner = DIM_HEAD*dim = 64*256 = 16384 (its own
    // "# 4096" comment is wrong). Stay adaptive to be safe.
    long long wq_elems = (long long)in_sizes[2];
    int inner = (int)(wq_elems / DIM);     // 16384 expected
    int dhead = inner / HEADS;             //  2048 expected

    float *xn, *q, *k, *v, *s, *o;
    cudaGetSymbolAddress((void**)&xn, g_xn);
    cudaGetSymbolAddress((void**)&q,  g_q);
    cudaGetSymbolAddress((void**)&k,  g_k);
    cudaGetSymbolAddress((void**)&v,  g_v);
    cudaGetSymbolAddress((void**)&s,  g_s);
    cudaGetSymbolAddress((void**)&o,  g_o);

    // 1) LayerNorm
    ln_kernel<<<TOK, 256>>>(x, gamma, xn);

    // 2) Q/K/V projections: (4096 x 256) @ (inner x 256)^T -> (4096 x inner), NT
    {
        dim3 grid(inner / 128, TOK / 128, 1);
        gemm_kernel<true><<<grid, 256>>>(xn, Wq, q, DIM,
                                         DIM, DIM, inner, 1,
                                         0, 0, 0, 0, 0, 0, 1.0f);
        gemm_kernel<true><<<grid, 256>>>(xn, Wk, k, DIM,
                                         DIM, DIM, inner, 1,
                                         0, 0, 0, 0, 0, 0, 1.0f);
        gemm_kernel<true><<<grid, 256>>>(xn, Wv, v, DIM,
                                         DIM, DIM, inner, 1,
                                         0, 0, 0, 0, 0, 0, 1.0f);
    }

    // 3) S = scale * q @ k^T per (b,h): M=N=2048, K=dhead, 16 batches, NT
    {
        dim3 grid(NTOK / 128, NTOK / 128, BATCH * HEADS);
        gemm_kernel<true><<<grid, 256>>>(
            q, k, s, dhead,
            inner, inner, NTOK, HEADS,
            (long long)NTOK * inner, dhead,          // A: q  (batch, head strides)
            (long long)NTOK * inner, dhead,          // B: k
            (long long)HEADS * NTOK * NTOK, (long long)NTOK * NTOK, // C: s
            ATT_SCALE);
    }

    // 4) softmax rows
    softmax_kernel<<<BATCH * HEADS * NTOK, 256>>>(s);

    // 5) O = P @ V per (b,h): M=2048, N=dhead, K=2048, NN
    {
        dim3 grid(dhead / 128, NTOK / 128, BATCH * HEADS);
        gemm_kernel<false><<<grid, 256>>>(
            s, v, o, NTOK,
            NTOK, inner, inner, HEADS,
            (long long)HEADS * NTOK * NTOK, (long long)NTOK * NTOK, // A: s
            (long long)NTOK * inner, dhead,                         // B: v
            (long long)NTOK * inner, dhead,                         // C: o
            1.0f);
    }

    // 6) out = O @ Wo^T: (4096 x inner) @ (256 x inner)^T -> (4096 x 256), NT
    {
        dim3 grid(DIM / 128, TOK / 128, 1);
        gemm_kernel<true><<<grid, 256>>>(o, Wo, out, inner,
                                         inner, inner, DIM, 1,
                                         0, 0, 0, 0, 0, 0, 1.0f);
    }
}

// round 5
// speedup vs baseline: 7.2494x; 7.2494x over previous
#include <cuda_runtime.h>
#include <math.h>

// Problem constants (confirmed R4: inner = DIM_HEAD*dim = 16384)
#define BATCH   2
#define NTOK    2048
#define DIM     256
#define HEADS   8
#define INNER   16384
#define DHEAD   2048              // INNER / HEADS
#define TOK     (BATCH*NTOK)      // 4096
#define ATT_SCALE 0.125f          // DIM_HEAD=64 -> 64^-0.5
#define LN_EPS  1e-5f

// ---------------- scratch (static device globals; no cudaMalloc allowed) ----
__device__ float g_xn[TOK * DIM];                            //    4 MB
__device__ float g_m [HEADS * DIM * DIM];                    //    2 MB  M_h = Wq_h^T Wk_h
__device__ float g_g [HEADS * DIM * DIM];                    //    2 MB  G_h = Wo_h Wv_h
__device__ float g_t [(size_t)BATCH * HEADS * NTOK * DIM];   //   32 MB  T = xn*M
__device__ float g_u [(size_t)BATCH * HEADS * NTOK * DIM];   //   32 MB  U = xn*G^T
__device__ float g_s [(size_t)BATCH * NTOK * INNER];         //  256 MB  S (b, q, h*2048+k)
__device__ float g_op[(size_t)BATCH * HEADS * NTOK * DIM];   //   32 MB  per-head out partials

// ---------------- LayerNorm:  xn = (x-mu)*rsqrt(var+eps)*(gamma+1) ----------
__global__ void ln_kernel(const float* __restrict__ x,
                          const float* __restrict__ gamma,
                          float* __restrict__ xn)
{
    int row = blockIdx.x;            // one token per block, 256 threads
    int t   = threadIdx.x;
    float v = x[row * DIM + t];

    __shared__ float s1[8], s2[8];
    float a = v, b = v * v;
    #pragma unroll
    for (int o = 16; o > 0; o >>= 1) {
        a += __shfl_xor_sync(0xffffffffu, a, o);
        b += __shfl_xor_sync(0xffffffffu, b, o);
    }
    int lane = t & 31, w = t >> 5;
    if (lane == 0) { s1[w] = a; s2[w] = b; }
    __syncthreads();
    if (t == 0) {
        float sa = 0.f, sb = 0.f;
        #pragma unroll
        for (int i = 0; i < 8; i++) { sa += s1[i]; sb += s2[i]; }
        s1[0] = sa * (1.0f / DIM);
        s2[0] = sb * (1.0f / DIM);
    }
    __syncthreads();
    float mu  = s1[0];
    float var = s2[0] - mu * mu;
    float r   = rsqrtf(var + LN_EPS);
    xn[row * DIM + t] = (v - mu) * r * (gamma[t] + 1.0f);
}

// ---------------- small 64x64 GEMM for 256x256xK head precomputes ----------
// AT=true  (TN): C[m][n] = sum_k A[k*lda + m] * B[k*ldb + n]
// AT=false (NN): C[m][n] = sum_k A[m*lda + k] * B[k*ldb + n]
// z = head; per-head element offsets sAh/sBh/sCh. Requires K%16==0.
template<bool AT>
__global__ void __launch_bounds__(256)
gemm64(const float* __restrict__ A, const float* __restrict__ B,
       float* __restrict__ C,
       int K, int lda, int ldb, int ldc,
       long long sAh, long long sBh, long long sCh)
{
    __shared__ float As[16][68];
    __shared__ float Bs[16][68];

    int h = blockIdx.z;
    const float* Ab = A + (long long)h * sAh;
    const float* Bb = B + (long long)h * sBh;
    float*       Cb = C + (long long)h * sCh;

    int m0 = blockIdx.y * 64;
    int n0 = blockIdx.x * 64;
    int tid = threadIdx.x;
    int tx = tid & 15;
    int ty = tid >> 4;

    float acc[4][4];
    #pragma unroll
    for (int i = 0; i < 4; i++)
        #pragma unroll
        for (int j = 0; j < 4; j++) acc[i][j] = 0.f;

    for (int k0 = 0; k0 < K; k0 += 16) {
        if (AT) {
            // A is (K, M) row-major: As[kk][mm] contiguous in mm
            int kk  = tid >> 4;           // 0..15
            int mm4 = (tid & 15) << 2;    // 0..60
            float4 a = *(const float4*)(Ab + (long long)(k0 + kk) * lda + m0 + mm4);
            *(float4*)&As[kk][mm4] = a;
        } else {
            // A is (M, K) row-major: transpose into As
            int mm = tid >> 2;            // 0..63
            int kq = (tid & 3) << 2;      // 0,4,8,12
            float4 a = *(const float4*)(Ab + (long long)(m0 + mm) * lda + k0 + kq);
            As[kq + 0][mm] = a.x;
            As[kq + 1][mm] = a.y;
            As[kq + 2][mm] = a.z;
            As[kq + 3][mm] = a.w;
        }
        {
            int kk  = tid >> 4;
            int nn4 = (tid & 15) << 2;
            float4 b = *(const float4*)(Bb + (long long)(k0 + kk) * ldb + n0 + nn4);
            *(float4*)&Bs[kk][nn4] = b;
        }
        __syncthreads();

        #pragma unroll
        for (int kk = 0; kk < 16; kk++) {
            float ra[4], rb[4];
            #pragma unroll
            for (int i = 0; i < 4; i++) ra[i] = As[kk][ty * 4 + i];
            #pragma unroll
            for (int j = 0; j < 4; j++) rb[j] = Bs[kk][tx * 4 + j];
            #pragma unroll
            for (int i = 0; i < 4; i++)
                #pragma unroll
                for (int j = 0; j < 4; j++)
                    acc[i][j] = fmaf(ra[i], rb[j], acc[i][j]);
        }
        __syncthreads();
    }

    #pragma unroll
    for (int i = 0; i < 4; i++)
        #pragma unroll
        for (int j = 0; j < 4; j++)
            Cb[(long long)(m0 + ty * 4 + i) * ldc + (n0 + tx * 4 + j)] = acc[i][j];
}

// ---------------- tiled FP32 GEMM (128x128x16, 8x8 microtile) --------------
// C[m][n] = alpha * sum_k A[m][k] * B'[k][n]
//   BT=true :  B row-major (N,K) -> B'[k][n] = B[n*ldb + k]   (NT)
//   BT=false:  B row-major (K,N) -> B'[k][n] = B[k*ldb + n]   (NN)
// Batch z = zb*hdiv + zh with independent base strides.
// Requires M%128==0, N%128==0, K%16==0.
template<bool BT>
__global__ void __launch_bounds__(256, 2)
gemm_kernel(const float* __restrict__ A, const float* __restrict__ B,
            float* __restrict__ C,
            int K, int lda, int ldb, int ldc,
            int hdiv,
            long long sAb, long long sAh,
            long long sBb, long long sBh,
            long long sCb, long long sCh,
            float alpha)
{
    const int BK = 16;
    __shared__ float As[BK][128];
    __shared__ float Bs[BK][128];

    int bz = blockIdx.z;
    int zb = bz / hdiv, zh = bz % hdiv;
    const float* Ab = A + (long long)zb * sAb + (long long)zh * sAh;
    const float* Bb = B + (long long)zb * sBb + (long long)zh * sBh;
    float*       Cb = C + (long long)zb * sCb + (long long)zh * sCh;

    int m0 = blockIdx.y * 128;
    int n0 = blockIdx.x * 128;
    int tid = threadIdx.x;
    int tx = tid & 15;
    int ty = tid >> 4;

    float acc[8][8];
    #pragma unroll
    for (int i = 0; i < 8; i++)
        #pragma unroll
        for (int j = 0; j < 8; j++) acc[i][j] = 0.f;

    for (int k0 = 0; k0 < K; k0 += BK) {
        {
            int r  = tid >> 2;
            int cg = (tid & 3) << 2;
            #pragma unroll
            for (int i = 0; i < 2; i++) {
                int row = r + i * 64;
                float4 a = *(const float4*)(Ab + (long long)(m0 + row) * lda + k0 + cg);
                As[cg + 0][row] = a.x;
                As[cg + 1][row] = a.y;
                As[cg + 2][row] = a.z;
                As[cg + 3][row] = a.w;
            }
        }
        if (BT) {
            int r  = tid >> 2;
            int cg = (tid & 3) << 2;
            #pragma unroll
            for (int i = 0; i < 2; i++) {
                int row = r + i * 64;
                float4 b = *(const float4*)(Bb + (long long)(n0 + row) * ldb + k0 + cg);
                Bs[cg + 0][row] = b.x;
                Bs[cg + 1][row] = b.y;
                Bs[cg + 2][row] = b.z;
                Bs[cg + 3][row] = b.w;
            }
        } else {
            int kk = tid >> 5;
            int ng = (tid & 31) << 2;
            #pragma unroll
            for (int i = 0; i < 2; i++) {
                int krow = kk + i * 8;
                float4 b = *(const float4*)(Bb + (long long)(k0 + krow) * ldb + n0 + ng);
                *(float4*)&Bs[krow][ng] = b;
            }
        }
        __syncthreads();

        #pragma unroll
        for (int kk = 0; kk < BK; kk++) {
            float ra[8], rb[8];
            *(float4*)&ra[0] = *(const float4*)&As[kk][ty * 8];
            *(float4*)&ra[4] = *(const float4*)&As[kk][ty * 8 + 4];
            *(float4*)&rb[0] = *(const float4*)&Bs[kk][tx * 8];
            *(float4*)&rb[4] = *(const float4*)&Bs[kk][tx * 8 + 4];
            #pragma unroll
            for (int i = 0; i < 8; i++)
                #pragma unroll
                for (int j = 0; j < 8; j++)
                    acc[i][j] = fmaf(ra[i], rb[j], acc[i][j]);
        }
        __syncthreads();
    }

    #pragma unroll
    for (int i = 0; i < 8; i++) {
        long long row = m0 + ty * 8 + i;
        #pragma unroll
        for (int j = 0; j < 8; j += 4) {
            float4 c;
            c.x = acc[i][j + 0] * alpha;
            c.y = acc[i][j + 1] * alpha;
            c.z = acc[i][j + 2] * alpha;
            c.w = acc[i][j + 3] * alpha;
            *(float4*)(Cb + row * ldc + n0 + tx * 8 + j) = c;
        }
    }
}

// ---------------- row softmax over 2048 contiguous columns -----------------
__global__ void softmax_kernel(float* __restrict__ S)
{
    size_t row = blockIdx.x;
    float* sr = S + row * (size_t)NTOK;
    int t = threadIdx.x;                 // 256 threads, 8 elems each

    float v[8];
    float m = -1e30f;
    #pragma unroll
    for (int i = 0; i < 8; i++) {
        v[i] = sr[t + 256 * i];
        m = fmaxf(m, v[i]);
    }

    __shared__ float sred[8];
    float w = m;
    #pragma unroll
    for (int o = 16; o > 0; o >>= 1) w = fmaxf(w, __shfl_xor_sync(0xffffffffu, w, o));
    if ((t & 31) == 0) sred[t >> 5] = w;
    __syncthreads();
    if (t == 0) {
        float z = sred[0];
        #pragma unroll
        for (int i = 1; i < 8; i++) z = fmaxf(z, sred[i]);
        sred[0] = z;
    }
    __syncthreads();
    m = sred[0];
    __syncthreads();

    float sum = 0.f;
    #pragma unroll
    for (int i = 0; i < 8; i++) {
        v[i] = __expf(v[i] - m);
        sum += v[i];
    }
    float w2 = sum;
    #pragma unroll
    for (int o = 16; o > 0; o >>= 1) w2 += __shfl_xor_sync(0xffffffffu, w2, o);
    if ((t & 31) == 0) sred[t >> 5] = w2;
    __syncthreads();
    if (t == 0) {
        float z = 0.f;
        #pragma unroll
        for (int i = 0; i < 8; i++) z += sred[i];
        sred[0] = z;
    }
    __syncthreads();
    float inv = 1.0f / sred[0];

    #pragma unroll
    for (int i = 0; i < 8; i++) sr[t + 256 * i] = v[i] * inv;
}

// ---------------- reduce per-head partials: out = sum_h op[b][h] -----------
__global__ void reduce_kernel(const float* __restrict__ op, float* __restrict__ out)
{
    int row = blockIdx.x;                // (b*2048 + q), 4096 rows
    int t   = threadIdx.x;               // 256 cols
    int b   = row >> 11;                 // /2048
    int q   = row & 2047;
    const float* base = op + (((long long)b * HEADS) * NTOK + q) * DIM + t;
    float acc = 0.f;
    #pragma unroll
    for (int h = 0; h < HEADS; h++)
        acc += base[(long long)h * NTOK * DIM];
    out[(long long)row * DIM + t] = acc;
}

// ---------------- launch ---------------------------------------------------
extern "C" void kernel_launch(void* const* d_in, const int* in_sizes, int n_in,
                              void* d_out, int out_size)
{
    const float* x     = (const float*)d_in[0];
    const float* gamma = (const float*)d_in[1];
    const float* Wq    = (const float*)d_in[2];
    const float* Wk    = (const float*)d_in[3];
    const float* Wv    = (const float*)d_in[4];
    const float* Wo    = (const float*)d_in[5];
    float* out = (float*)d_out;

    float *xn, *mh, *gh, *tt, *uu, *s, *op;
    cudaGetSymbolAddress((void**)&xn, g_xn);
    cudaGetSymbolAddress((void**)&mh, g_m);
    cudaGetSymbolAddress((void**)&gh, g_g);
    cudaGetSymbolAddress((void**)&tt, g_t);
    cudaGetSymbolAddress((void**)&uu, g_u);
    cudaGetSymbolAddress((void**)&s,  g_s);
    cudaGetSymbolAddress((void**)&op, g_op);

    const long long TD  = (long long)NTOK * DIM;        // 2048*256
    const long long HTD = (long long)HEADS * TD;        // per-batch T/U/op stride
    const long long SB  = (long long)NTOK * INNER;      // per-batch S stride

    // 1) LayerNorm
    ln_kernel<<<TOK, 256>>>(x, gamma, xn);

    // 2a) M_h = Wq_h^T * Wk_h   (256x256, K=2048, TN)
    {
        dim3 grid(4, 4, HEADS);
        gemm64<true><<<grid, 256>>>(Wq, Wk, mh, DHEAD, DIM, DIM, DIM,
                                    (long long)DHEAD * DIM,
                                    (long long)DHEAD * DIM,
                                    (long long)DIM * DIM);
    }
    // 2b) G_h = Wo_h * Wv_h     (256x256, K=2048, NN; Wo_h = Wo[:, h*2048:...])
    {
        dim3 grid(4, 4, HEADS);
        gemm64<false><<<grid, 256>>>(Wo, Wv, gh, DHEAD, INNER, DIM, DIM,
                                     (long long)DHEAD,
                                     (long long)DHEAD * DIM,
                                     (long long)DIM * DIM);
    }

    // 3) T[b][h] = xn_b * M_h   (2048x256, K=256, NN)
    {
        dim3 grid(DIM / 128, NTOK / 128, BATCH * HEADS);
        gemm_kernel<false><<<grid, 256>>>(
            xn, mh, tt, DIM, DIM, DIM, DIM, HEADS,
            TD, 0,                               // A: xn per batch
            0, (long long)DIM * DIM,             // B: M per head
            HTD, TD,                             // C: T[b][h]
            1.0f);
    }

    // 4) S[b][q][h*2048+k] = scale * T[b][h] * xn_b^T  (2048x2048, K=256, NT)
    {
        dim3 grid(NTOK / 128, NTOK / 128, BATCH * HEADS);
        gemm_kernel<true><<<grid, 256>>>(
            tt, xn, s, DIM, DIM, DIM, INNER, HEADS,
            HTD, TD,                             // A: T[b][h]
            TD, 0,                               // B: xn per batch
            SB, (long long)DHEAD,                // C: column block h*2048
            ATT_SCALE);
    }

    // 5) softmax over each contiguous 2048-row
    softmax_kernel<<<BATCH * NTOK * HEADS, 256>>>(s);

    // 6) U[b][h] = xn_b * G_h^T  (2048x256, K=256, NT)
    {
        dim3 grid(DIM / 128, NTOK / 128, BATCH * HEADS);
        gemm_kernel<true><<<grid, 256>>>(
            xn, gh, uu, DIM, DIM, DIM, DIM, HEADS,
            TD, 0,
            0, (long long)DIM * DIM,
            HTD, TD,
            1.0f);
    }

    // 7) op[b][h] = P[b][h] * U[b][h]  (2048x256, K=2048, NN)
    {
        dim3 grid(DIM / 128, NTOK / 128, BATCH * HEADS);
        gemm_kernel<false><<<grid, 256>>>(
            s, uu, op, NTOK, INNER, DIM, DIM, HEADS,
            SB, (long long)DHEAD,                // A: P rows, head column block
            HTD, TD,                             // B: U[b][h]
            HTD, TD,                             // C: op[b][h]
            1.0f);
    }

    // 8) out = sum_h op[b][h]
    reduce_kernel<<<TOK, 256>>>(op, out);
}

// round 6
// speedup vs baseline: 12.4778x; 1.7212x over previous
#include <cuda_runtime.h>
#include <cuda_bf16.h>
#include <math.h>
#include <stdint.h>

// Problem constants (confirmed: inner = DIM_HEAD*dim = 16384)
#define BATCH   2
#define NTOK    2048
#define DIM     256
#define HEADS   8
#define INNER   16384
#define DHEAD   2048              // INNER / HEADS
#define TOK     (BATCH*NTOK)      // 4096
#define ATT_SCALE 0.125f
#define LN_EPS  1e-5f

// ---------------- scratch (static device globals) --------------------------
__device__ float g_xn[TOK * DIM];                              //    4 MB
__device__ float g_m [HEADS * DIM * DIM];                      //    2 MB
__device__ float g_g [HEADS * DIM * DIM];                      //    2 MB
__device__ float g_t [(size_t)BATCH * HEADS * NTOK * DIM];     //   32 MB  T = xn*M
__device__ float g_ut[(size_t)BATCH * HEADS * DIM * NTOK];     //   32 MB  Ut = G*xn^T
__device__ float g_s [(size_t)BATCH * NTOK * INNER];           //  256 MB  logits
__device__ float g_op[(size_t)BATCH * HEADS * NTOK * DIM];     //   32 MB  per-head partials

__device__ __nv_bfloat16 g_xnh[TOK * DIM];
__device__ __nv_bfloat16 g_xnl[TOK * DIM];
__device__ __nv_bfloat16 g_th [(size_t)BATCH * HEADS * NTOK * DIM];
__device__ __nv_bfloat16 g_tl [(size_t)BATCH * HEADS * NTOK * DIM];
__device__ __nv_bfloat16 g_uth[(size_t)BATCH * HEADS * DIM * NTOK];
__device__ __nv_bfloat16 g_utl[(size_t)BATCH * HEADS * DIM * NTOK];
__device__ __nv_bfloat16 g_ph [(size_t)BATCH * NTOK * INNER];  //  128 MB
__device__ __nv_bfloat16 g_pl [(size_t)BATCH * NTOK * INNER];  //  128 MB

// ---------------- LayerNorm -------------------------------------------------
__global__ void ln_kernel(const float* __restrict__ x,
                          const float* __restrict__ gamma,
                          float* __restrict__ xn)
{
    int row = blockIdx.x;
    int t   = threadIdx.x;
    float v = x[row * DIM + t];

    __shared__ float s1[8], s2[8];
    float a = v, b = v * v;
    #pragma unroll
    for (int o = 16; o > 0; o >>= 1) {
        a += __shfl_xor_sync(0xffffffffu, a, o);
        b += __shfl_xor_sync(0xffffffffu, b, o);
    }
    int lane = t & 31, w = t >> 5;
    if (lane == 0) { s1[w] = a; s2[w] = b; }
    __syncthreads();
    if (t == 0) {
        float sa = 0.f, sb = 0.f;
        #pragma unroll
        for (int i = 0; i < 8; i++) { sa += s1[i]; sb += s2[i]; }
        s1[0] = sa * (1.0f / DIM);
        s2[0] = sb * (1.0f / DIM);
    }
    __syncthreads();
    float mu  = s1[0];
    float var = s2[0] - mu * mu;
    float r   = rsqrtf(var + LN_EPS);
    xn[row * DIM + t] = (v - mu) * r * (gamma[t] + 1.0f);
}

// ---------------- fp32 -> bf16 hi/lo split ----------------------------------
__global__ void split_kernel(const float* __restrict__ src,
                             __nv_bfloat16* __restrict__ hi,
                             __nv_bfloat16* __restrict__ lo,
                             long long n4)   // n/4
{
    long long i = ((long long)blockIdx.x * blockDim.x + threadIdx.x);
    if (i >= n4) return;
    long long e = i * 4;
    float4 v = *(const float4*)(src + e);
    __nv_bfloat16 h0 = __float2bfloat16(v.x);
    __nv_bfloat16 h1 = __float2bfloat16(v.y);
    __nv_bfloat16 h2 = __float2bfloat16(v.z);
    __nv_bfloat16 h3 = __float2bfloat16(v.w);
    __nv_bfloat16 l0 = __float2bfloat16(v.x - __bfloat162float(h0));
    __nv_bfloat16 l1 = __float2bfloat16(v.y - __bfloat162float(h1));
    __nv_bfloat16 l2 = __float2bfloat16(v.z - __bfloat162float(h2));
    __nv_bfloat16 l3 = __float2bfloat16(v.w - __bfloat162float(h3));
    ((__nv_bfloat162*)(hi + e))[0] = __nv_bfloat162{h0, h1};
    ((__nv_bfloat162*)(hi + e))[1] = __nv_bfloat162{h2, h3};
    ((__nv_bfloat162*)(lo + e))[0] = __nv_bfloat162{l0, l1};
    ((__nv_bfloat162*)(lo + e))[1] = __nv_bfloat162{l2, l3};
}

// ---------------- small 64x64 GEMM for head precomputes ---------------------
template<bool AT>
__global__ void __launch_bounds__(256)
gemm64(const float* __restrict__ A, const float* __restrict__ B,
       float* __restrict__ C,
       int K, int lda, int ldb, int ldc,
       long long sAh, long long sBh, long long sCh)
{
    __shared__ float As[16][68];
    __shared__ float Bs[16][68];

    int h = blockIdx.z;
    const float* Ab = A + (long long)h * sAh;
    const float* Bb = B + (long long)h * sBh;
    float*       Cb = C + (long long)h * sCh;

    int m0 = blockIdx.y * 64;
    int n0 = blockIdx.x * 64;
    int tid = threadIdx.x;
    int tx = tid & 15;
    int ty = tid >> 4;

    float acc[4][4];
    #pragma unroll
    for (int i = 0; i < 4; i++)
        #pragma unroll
        for (int j = 0; j < 4; j++) acc[i][j] = 0.f;

    for (int k0 = 0; k0 < K; k0 += 16) {
        if (AT) {
            int kk  = tid >> 4;
            int mm4 = (tid & 15) << 2;
            float4 a = *(const float4*)(Ab + (long long)(k0 + kk) * lda + m0 + mm4);
            *(float4*)&As[kk][mm4] = a;
        } else {
            int mm = tid >> 2;
            int kq = (tid & 3) << 2;
            float4 a = *(const float4*)(Ab + (long long)(m0 + mm) * lda + k0 + kq);
            As[kq + 0][mm] = a.x;
            As[kq + 1][mm] = a.y;
            As[kq + 2][mm] = a.z;
            As[kq + 3][mm] = a.w;
        }
        {
            int kk  = tid >> 4;
            int nn4 = (tid & 15) << 2;
            float4 b = *(const float4*)(Bb + (long long)(k0 + kk) * ldb + n0 + nn4);
            *(float4*)&Bs[kk][nn4] = b;
        }
        __syncthreads();

        #pragma unroll
        for (int kk = 0; kk < 16; kk++) {
            float ra[4], rb[4];
            #pragma unroll
            for (int i = 0; i < 4; i++) ra[i] = As[kk][ty * 4 + i];
            #pragma unroll
            for (int j = 0; j < 4; j++) rb[j] = Bs[kk][tx * 4 + j];
            #pragma unroll
            for (int i = 0; i < 4; i++)
                #pragma unroll
                for (int j = 0; j < 4; j++)
                    acc[i][j] = fmaf(ra[i], rb[j], acc[i][j]);
        }
        __syncthreads();
    }

    #pragma unroll
    for (int i = 0; i < 4; i++)
        #pragma unroll
        for (int j = 0; j < 4; j++)
            Cb[(long long)(m0 + ty * 4 + i) * ldc + (n0 + tx * 4 + j)] = acc[i][j];
}

// ---------------- fp32 tiled GEMM (for T and Ut) -----------------------------
template<bool BT>
__global__ void __launch_bounds__(256, 2)
gemm_kernel(const float* __restrict__ A, const float* __restrict__ B,
            float* __restrict__ C,
            int K, int lda, int ldb, int ldc,
            int hdiv,
            long long sAb, long long sAh,
            long long sBb, long long sBh,
            long long sCb, long long sCh,
            float alpha)
{
    const int BK = 16;
    __shared__ float As[BK][128];
    __shared__ float Bs[BK][128];

    int bz = blockIdx.z;
    int zb = bz / hdiv, zh = bz % hdiv;
    const float* Ab = A + (long long)zb * sAb + (long long)zh * sAh;
    const float* Bb = B + (long long)zb * sBb + (long long)zh * sBh;
    float*       Cb = C + (long long)zb * sCb + (long long)zh * sCh;

    int m0 = blockIdx.y * 128;
    int n0 = blockIdx.x * 128;
    int tid = threadIdx.x;
    int tx = tid & 15;
    int ty = tid >> 4;

    float acc[8][8];
    #pragma unroll
    for (int i = 0; i < 8; i++)
        #pragma unroll
        for (int j = 0; j < 8; j++) acc[i][j] = 0.f;

    for (int k0 = 0; k0 < K; k0 += BK) {
        {
            int r  = tid >> 2;
            int cg = (tid & 3) << 2;
            #pragma unroll
            for (int i = 0; i < 2; i++) {
                int row = r + i * 64;
                float4 a = *(const float4*)(Ab + (long long)(m0 + row) * lda + k0 + cg);
                As[cg + 0][row] = a.x;
                As[cg + 1][row] = a.y;
                As[cg + 2][row] = a.z;
                As[cg + 3][row] = a.w;
            }
        }
        if (BT) {
            int r  = tid >> 2;
            int cg = (tid & 3) << 2;
            #pragma unroll
            for (int i = 0; i < 2; i++) {
                int row = r + i * 64;
                float4 b = *(const float4*)(Bb + (long long)(n0 + row) * ldb + k0 + cg);
                Bs[cg + 0][row] = b.x;
                Bs[cg + 1][row] = b.y;
                Bs[cg + 2][row] = b.z;
                Bs[cg + 3][row] = b.w;
            }
        } else {
            int kk = tid >> 5;
            int ng = (tid & 31) << 2;
            #pragma unroll
            for (int i = 0; i < 2; i++) {
                int krow = kk + i * 8;
                float4 b = *(const float4*)(Bb + (long long)(k0 + krow) * ldb + n0 + ng);
                *(float4*)&Bs[krow][ng] = b;
            }
        }
        __syncthreads();

        #pragma unroll
        for (int kk = 0; kk < BK; kk++) {
            float ra[8], rb[8];
            *(float4*)&ra[0] = *(const float4*)&As[kk][ty * 8];
            *(float4*)&ra[4] = *(const float4*)&As[kk][ty * 8 + 4];
            *(float4*)&rb[0] = *(const float4*)&Bs[kk][tx * 8];
            *(float4*)&rb[4] = *(const float4*)&Bs[kk][tx * 8 + 4];
            #pragma unroll
            for (int i = 0; i < 8; i++)
                #pragma unroll
                for (int j = 0; j < 8; j++)
                    acc[i][j] = fmaf(ra[i], rb[j], acc[i][j]);
        }
        __syncthreads();
    }

    #pragma unroll
    for (int i = 0; i < 8; i++) {
        long long row = m0 + ty * 8 + i;
        #pragma unroll
        for (int j = 0; j < 8; j += 4) {
            float4 c;
            c.x = acc[i][j + 0] * alpha;
            c.y = acc[i][j + 1] * alpha;
            c.z = acc[i][j + 2] * alpha;
            c.w = acc[i][j + 3] * alpha;
            *(float4*)(Cb + row * ldc + n0 + tx * 8 + j) = c;
        }
    }
}

// ---------------- bf16 split tensor-core GEMM (NT) --------------------------
// C[m][n] = alpha * sum_k (Ahi*Bhi + Ahi*Blo + Alo*Bhi)[m][k][n]
// A row-major (M,K), B row-major (N,K), bf16; C fp32.
// Block 128x128, 8 warps of 32x64, k-chunk 32.
#define LDSB 40
__device__ __forceinline__ void ldsm4(uint32_t* d, const __nv_bfloat16* p)
{
    uint32_t a = (uint32_t)__cvta_generic_to_shared(p);
    asm volatile("ldmatrix.sync.aligned.m8n8.x4.shared.b16 {%0,%1,%2,%3}, [%4];"
                 : "=r"(d[0]), "=r"(d[1]), "=r"(d[2]), "=r"(d[3]) : "r"(a));
}
__device__ __forceinline__ void mma16816(float* d, const uint32_t* a, const uint32_t* b)
{
    asm volatile(
        "mma.sync.aligned.m16n8k16.row.col.f32.bf16.bf16.f32 "
        "{%0,%1,%2,%3}, {%4,%5,%6,%7}, {%8,%9}, {%0,%1,%2,%3};"
        : "+f"(d[0]), "+f"(d[1]), "+f"(d[2]), "+f"(d[3])
        : "r"(a[0]), "r"(a[1]), "r"(a[2]), "r"(a[3]), "r"(b[0]), "r"(b[1]));
}

__global__ void __launch_bounds__(256)
mma_nt(const __nv_bfloat16* __restrict__ Ahi, const __nv_bfloat16* __restrict__ Alo,
       const __nv_bfloat16* __restrict__ Bhi, const __nv_bfloat16* __restrict__ Blo,
       float* __restrict__ C,
       int K, int lda, int ldb, int ldc,
       int hdiv,
       long long sAb, long long sAh,
       long long sBb, long long sBh,
       long long sCb, long long sCh,
       float alpha)
{
    __shared__ __align__(16) __nv_bfloat16 Ash[128][LDSB];
    __shared__ __align__(16) __nv_bfloat16 Asl[128][LDSB];
    __shared__ __align__(16) __nv_bfloat16 Bsh[128][LDSB];
    __shared__ __align__(16) __nv_bfloat16 Bsl[128][LDSB];

    int bz = blockIdx.z;
    int zb = bz / hdiv, zh = bz % hdiv;
    long long aoff = (long long)zb * sAb + (long long)zh * sAh;
    long long boff = (long long)zb * sBb + (long long)zh * sBh;
    const __nv_bfloat16* Ah = Ahi + aoff;
    const __nv_bfloat16* Al = Alo + aoff;
    const __nv_bfloat16* Bh = Bhi + boff;
    const __nv_bfloat16* Bl = Blo + boff;
    float* Cb = C + (long long)zb * sCb + (long long)zh * sCh;

    int m0 = blockIdx.y * 128;
    int n0 = blockIdx.x * 128;
    int tid  = threadIdx.x;
    int warp = tid >> 5;
    int lane = tid & 31;
    int wm = (warp & 3) * 32;      // warp row in block tile
    int wn = (warp >> 2) * 64;     // warp col in block tile

    float acc[2][8][4];
    #pragma unroll
    for (int i = 0; i < 2; i++)
        #pragma unroll
        for (int j = 0; j < 8; j++)
            #pragma unroll
            for (int c = 0; c < 4; c++) acc[i][j][c] = 0.f;

    int r  = tid >> 2;            // 0..63
    int kc = (tid & 3) * 8;       // 0,8,16,24

    for (int k0 = 0; k0 < K; k0 += 32) {
        #pragma unroll
        for (int i = 0; i < 2; i++) {
            int row = r + i * 64;
            long long ga = (long long)(m0 + row) * lda + k0 + kc;
            long long gb = (long long)(n0 + row) * ldb + k0 + kc;
            *(uint4*)&Ash[row][kc] = *(const uint4*)(Ah + ga);
            *(uint4*)&Asl[row][kc] = *(const uint4*)(Al + ga);
            *(uint4*)&Bsh[row][kc] = *(const uint4*)(Bh + gb);
            *(uint4*)&Bsl[row][kc] = *(const uint4*)(Bl + gb);
        }
        __syncthreads();

        #pragma unroll
        for (int s = 0; s < 32; s += 16) {
            // A fragments (2 m-tiles), hi and lo
            uint32_t ah[2][4], al[2][4];
            #pragma unroll
            for (int i = 0; i < 2; i++) {
                int row = wm + i * 16 + (lane & 15);
                int col = s + ((lane >> 4) << 3);
                ldsm4(ah[i], &Ash[row][col]);
                ldsm4(al[i], &Asl[row][col]);
            }
            // B fragments: 4 ldmatrix.x4, each covers 2 n-tiles
            #pragma unroll
            for (int j = 0; j < 4; j++) {
                int row = wn + j * 16 + ((lane >> 4) << 3) + (lane & 7);
                int col = s + ((lane >> 3) & 1) * 8;
                uint32_t bh[4], bl[4];
                ldsm4(bh, &Bsh[row][col]);
                ldsm4(bl, &Bsl[row][col]);
                #pragma unroll
                for (int jj = 0; jj < 2; jj++) {
                    #pragma unroll
                    for (int i = 0; i < 2; i++) {
                        mma16816(acc[i][j * 2 + jj], ah[i], bh + jj * 2);
                        mma16816(acc[i][j * 2 + jj], ah[i], bl + jj * 2);
                        mma16816(acc[i][j * 2 + jj], al[i], bh + jj * 2);
                    }
                }
            }
        }
        __syncthreads();
    }

    // epilogue: c0,c1 -> (row, col..col+1); c2,c3 -> (row+8, col..col+1)
    #pragma unroll
    for (int i = 0; i < 2; i++) {
        #pragma unroll
        for (int j = 0; j < 8; j++) {
            int row = m0 + wm + i * 16 + (lane >> 2);
            int col = n0 + wn + j * 8 + (lane & 3) * 2;
            float2 v0 = { alpha * acc[i][j][0], alpha * acc[i][j][1] };
            float2 v1 = { alpha * acc[i][j][2], alpha * acc[i][j][3] };
            *(float2*)(Cb + (long long)row * ldc + col)       = v0;
            *(float2*)(Cb + (long long)(row + 8) * ldc + col) = v1;
        }
    }
}

// ---------------- row softmax (2048 cols) + bf16 hi/lo split ----------------
__global__ void softmax_split_kernel(const float* __restrict__ S,
                                     __nv_bfloat16* __restrict__ Phi,
                                     __nv_bfloat16* __restrict__ Plo)
{
    size_t row = blockIdx.x;
    const float* sr = S + row * (size_t)NTOK;
    int t = threadIdx.x;

    float v[8];
    float m = -1e30f;
    #pragma unroll
    for (int i = 0; i < 8; i++) {
        v[i] = sr[t + 256 * i];
        m = fmaxf(m, v[i]);
    }

    __shared__ float sred[8];
    float w = m;
    #pragma unroll
    for (int o = 16; o > 0; o >>= 1) w = fmaxf(w, __shfl_xor_sync(0xffffffffu, w, o));
    if ((t & 31) == 0) sred[t >> 5] = w;
    __syncthreads();
    if (t == 0) {
        float z = sred[0];
        #pragma unroll
        for (int i = 1; i < 8; i++) z = fmaxf(z, sred[i]);
        sred[0] = z;
    }
    __syncthreads();
    m = sred[0];
    __syncthreads();

    float sum = 0.f;
    #pragma unroll
    for (int i = 0; i < 8; i++) {
        v[i] = __expf(v[i] - m);
        sum += v[i];
    }
    float w2 = sum;
    #pragma unroll
    for (int o = 16; o > 0; o >>= 1) w2 += __shfl_xor_sync(0xffffffffu, w2, o);
    if ((t & 31) == 0) sred[t >> 5] = w2;
    __syncthreads();
    if (t == 0) {
        float z = 0.f;
        #pragma unroll
        for (int i = 0; i < 8; i++) z += sred[i];
        sred[0] = z;
    }
    __syncthreads();
    float inv = 1.0f / sred[0];

    size_t base = row * (size_t)NTOK;
    #pragma unroll
    for (int i = 0; i < 8; i++) {
        float p = v[i] * inv;
        __nv_bfloat16 h = __float2bfloat16(p);
        Phi[base + t + 256 * i] = h;
        Plo[base + t + 256 * i] = __float2bfloat16(p - __bfloat162float(h));
    }
}

// ---------------- reduce per-head partials ----------------------------------
__global__ void reduce_kernel(const float* __restrict__ op, float* __restrict__ out)
{
    int row = blockIdx.x;
    int t   = threadIdx.x;
    int b   = row >> 11;
    int q   = row & 2047;
    const float* base = op + (((long long)b * HEADS) * NTOK + q) * DIM + t;
    float acc = 0.f;
    #pragma unroll
    for (int h = 0; h < HEADS; h++)
        acc += base[(long long)h * NTOK * DIM];
    out[(long long)row * DIM + t] = acc;
}

// ---------------- launch ----------------------------------------------------
extern "C" void kernel_launch(void* const* d_in, const int* in_sizes, int n_in,
                              void* d_out, int out_size)
{
    const float* x     = (const float*)d_in[0];
    const float* gamma = (const float*)d_in[1];
    const float* Wq    = (const float*)d_in[2];
    const float* Wk    = (const float*)d_in[3];
    const float* Wv    = (const float*)d_in[4];
    const float* Wo    = (const float*)d_in[5];
    float* out = (float*)d_out;

    float *xn, *mh, *gh, *tt, *ut, *s, *op;
    __nv_bfloat16 *xnh, *xnl, *th, *tl, *uth, *utl, *ph, *pl;
    cudaGetSymbolAddress((void**)&xn,  g_xn);
    cudaGetSymbolAddress((void**)&mh,  g_m);
    cudaGetSymbolAddress((void**)&gh,  g_g);
    cudaGetSymbolAddress((void**)&tt,  g_t);
    cudaGetSymbolAddress((void**)&ut,  g_ut);
    cudaGetSymbolAddress((void**)&s,   g_s);
    cudaGetSymbolAddress((void**)&op,  g_op);
    cudaGetSymbolAddress((void**)&xnh, g_xnh);
    cudaGetSymbolAddress((void**)&xnl, g_xnl);
    cudaGetSymbolAddress((void**)&th,  g_th);
    cudaGetSymbolAddress((void**)&tl,  g_tl);
    cudaGetSymbolAddress((void**)&uth, g_uth);
    cudaGetSymbolAddress((void**)&utl, g_utl);
    cudaGetSymbolAddress((void**)&ph,  g_ph);
    cudaGetSymbolAddress((void**)&pl,  g_pl);

    const long long TD  = (long long)NTOK * DIM;
    const long long HTD = (long long)HEADS * TD;
    const long long SB  = (long long)NTOK * INNER;
    const long long DD  = (long long)DIM * DIM;

    // 1) LayerNorm + split
    ln_kernel<<<TOK, 256>>>(x, gamma, xn);
    split_kernel<<<(TOK * DIM / 4 + 255) / 256, 256>>>(xn, xnh, xnl, TOK * DIM / 4);

    // 2) M_h = Wq_h^T Wk_h ; G_h = Wo_h Wv_h
    {
        dim3 grid(4, 4, HEADS);
        gemm64<true><<<grid, 256>>>(Wq, Wk, mh, DHEAD, DIM, DIM, DIM,
                                    (long long)DHEAD * DIM, (long long)DHEAD * DIM, DD);
        gemm64<false><<<grid, 256>>>(Wo, Wv, gh, DHEAD, INNER, DIM, DIM,
                                     (long long)DHEAD, (long long)DHEAD * DIM, DD);
    }

    // 3) T[b][h] = xn_b * M_h  (fp32), then split
    {
        dim3 grid(DIM / 128, NTOK / 128, BATCH * HEADS);
        gemm_kernel<false><<<grid, 256>>>(
            xn, mh, tt, DIM, DIM, DIM, DIM, HEADS,
            TD, 0, 0, DD, HTD, TD, 1.0f);
    }
    split_kernel<<<(int)((BATCH * HTD / 4 + 255) / 256), 256>>>(tt, th, tl, BATCH * HTD / 4);

    // 4) S = scale * T * xn^T  (bf16 split tensor cores)
    {
        dim3 grid(NTOK / 128, NTOK / 128, BATCH * HEADS);
        mma_nt<<<grid, 256>>>(
            th, tl, xnh, xnl, s,
            DIM, DIM, DIM, INNER, HEADS,
            HTD, TD,                 // A strides (batch, head)
            TD, 0,                   // B strides
            SB, (long long)DHEAD,    // C strides
            ATT_SCALE);
    }

    // 5) softmax + P split
    softmax_split_kernel<<<BATCH * NTOK * HEADS, 256>>>(s, ph, pl);

    // 6) Ut[b][h] = G_h * xn_b^T  (fp32, 256 x 2048), then split
    {
        dim3 grid(NTOK / 128, DIM / 128, BATCH * HEADS);
        gemm_kernel<true><<<grid, 256>>>(
            gh, xn, ut, DIM, DIM, DIM, NTOK, HEADS,
            0, DD,                   // A: G per head
            TD, 0,                   // B: xn per batch
            HTD, TD,                 // C: Ut[b][h]
            1.0f);
    }
    split_kernel<<<(int)((BATCH * HTD / 4 + 255) / 256), 256>>>(ut, uth, utl, BATCH * HTD / 4);

    // 7) op[b][h] = P[b][h] * Ut[b][h]^T  (bf16 split tensor cores, NT)
    {
        dim3 grid(DIM / 128, NTOK / 128, BATCH * HEADS);
        mma_nt<<<grid, 256>>>(
            ph, pl, uth, utl, op,
            NTOK, INNER, NTOK, DIM, HEADS,
            SB, (long long)DHEAD,    // A: P rows, head column block
            HTD, TD,                 // B: Ut[b][h]
            HTD, TD,                 // C: op[b][h]
            1.0f);
    }

    // 8) out = sum_h op[b][h]
    reduce_kernel<<<TOK, 256>>>(op, out);
}

// round 7
// speedup vs baseline: 15.9932x; 1.2817x over previous
#include <cuda_runtime.h>
#include <cuda_bf16.h>
#include <math.h>
#include <stdint.h>

// Problem constants (confirmed: inner = DIM_HEAD*dim = 16384)
#define BATCH   2
#define NTOK    2048
#define DIM     256
#define HEADS   8
#define INNER   16384
#define DHEAD   2048              // INNER / HEADS
#define TOK     (BATCH*NTOK)      // 4096
#define ATT_SCALE 0.125f
#define LN_EPS  1e-5f
#define NSPLIT  8                 // split-K factor for precomputes
#define KS      (DHEAD/NSPLIT)    // 256

// ---------------- scratch (static device globals) --------------------------
__device__ float g_xn[TOK * DIM];                              //    4 MB
__device__ float g_pm[(size_t)HEADS * NSPLIT * DIM * DIM];     //   16 MB  Mt partials
__device__ float g_pg[(size_t)HEADS * NSPLIT * DIM * DIM];     //   16 MB  G  partials
__device__ float g_t [(size_t)BATCH * HEADS * NTOK * DIM];     //   32 MB  T = xn*M
__device__ float g_ut[(size_t)BATCH * HEADS * DIM * NTOK];     //   32 MB  Ut = G*xn^T
__device__ float g_s [(size_t)BATCH * NTOK * INNER];           //  256 MB  logits
__device__ float g_op[(size_t)BATCH * HEADS * NTOK * DIM];     //   32 MB  per-head partials

__device__ __nv_bfloat16 g_xnh[TOK * DIM];
__device__ __nv_bfloat16 g_xnl[TOK * DIM];
__device__ __nv_bfloat16 g_mth[HEADS * DIM * DIM];
__device__ __nv_bfloat16 g_mtl[HEADS * DIM * DIM];
__device__ __nv_bfloat16 g_gh_[HEADS * DIM * DIM];
__device__ __nv_bfloat16 g_gl_[HEADS * DIM * DIM];
__device__ __nv_bfloat16 g_th [(size_t)BATCH * HEADS * NTOK * DIM];
__device__ __nv_bfloat16 g_tl [(size_t)BATCH * HEADS * NTOK * DIM];
__device__ __nv_bfloat16 g_uth[(size_t)BATCH * HEADS * DIM * NTOK];
__device__ __nv_bfloat16 g_utl[(size_t)BATCH * HEADS * DIM * NTOK];
__device__ __nv_bfloat16 g_ph [(size_t)BATCH * NTOK * INNER];  //  128 MB
__device__ __nv_bfloat16 g_pl [(size_t)BATCH * NTOK * INNER];  //  128 MB

// ---------------- LayerNorm -------------------------------------------------
__global__ void ln_kernel(const float* __restrict__ x,
                          const float* __restrict__ gamma,
                          float* __restrict__ xn)
{
    int row = blockIdx.x;
    int t   = threadIdx.x;
    float v = x[row * DIM + t];

    __shared__ float s1[8], s2[8];
    float a = v, b = v * v;
    #pragma unroll
    for (int o = 16; o > 0; o >>= 1) {
        a += __shfl_xor_sync(0xffffffffu, a, o);
        b += __shfl_xor_sync(0xffffffffu, b, o);
    }
    int lane = t & 31, w = t >> 5;
    if (lane == 0) { s1[w] = a; s2[w] = b; }
    __syncthreads();
    if (t == 0) {
        float sa = 0.f, sb = 0.f;
        #pragma unroll
        for (int i = 0; i < 8; i++) { sa += s1[i]; sb += s2[i]; }
        s1[0] = sa * (1.0f / DIM);
        s2[0] = sb * (1.0f / DIM);
    }
    __syncthreads();
    float mu  = s1[0];
    float var = s2[0] - mu * mu;
    float r   = rsqrtf(var + LN_EPS);
    xn[row * DIM + t] = (v - mu) * r * (gamma[t] + 1.0f);
}

// ---------------- fp32 -> bf16 hi/lo split ----------------------------------
__global__ void split_kernel(const float* __restrict__ src,
                             __nv_bfloat16* __restrict__ hi,
                             __nv_bfloat16* __restrict__ lo,
                             long long n4)
{
    long long i = ((long long)blockIdx.x * blockDim.x + threadIdx.x);
    if (i >= n4) return;
    long long e = i * 4;
    float4 v = *(const float4*)(src + e);
    __nv_bfloat16 h0 = __float2bfloat16(v.x);
    __nv_bfloat16 h1 = __float2bfloat16(v.y);
    __nv_bfloat16 h2 = __float2bfloat16(v.z);
    __nv_bfloat16 h3 = __float2bfloat16(v.w);
    __nv_bfloat16 l0 = __float2bfloat16(v.x - __bfloat162float(h0));
    __nv_bfloat16 l1 = __float2bfloat16(v.y - __bfloat162float(h1));
    __nv_bfloat16 l2 = __float2bfloat16(v.z - __bfloat162float(h2));
    __nv_bfloat16 l3 = __float2bfloat16(v.w - __bfloat162float(h3));
    ((__nv_bfloat162*)(hi + e))[0] = __nv_bfloat162{h0, h1};
    ((__nv_bfloat162*)(hi + e))[1] = __nv_bfloat162{h2, h3};
    ((__nv_bfloat162*)(lo + e))[0] = __nv_bfloat162{l0, l1};
    ((__nv_bfloat162*)(lo + e))[1] = __nv_bfloat162{l2, l3};
}

// ---------------- split-K 64x64 GEMM for head precomputes --------------------
// z = h*NSPLIT + s; computes a KS-chunk partial of the 256x256 per-head GEMM.
// AT=true  (TN): C[m][n] += sum_k A[(hk0+k)*lda + m] * B[(hk0+k)*ldb + n]
// AT=false (NN): C[m][n] += sum_k A[m*lda + hk0 + k] * B[(hk0+k)*ldb + n]
//   where hk0 = h*DHEAD + s*KS.
template<bool AT>
__global__ void __launch_bounds__(256)
gemm64_sk(const float* __restrict__ A, const float* __restrict__ B,
          float* __restrict__ Cp, int lda, int ldb)
{
    __shared__ float As[16][68];
    __shared__ float Bs[16][68];

    int z = blockIdx.z;
    int h = z / NSPLIT, sp = z % NSPLIT;
    long long hk0 = (long long)h * DHEAD + (long long)sp * KS;

    const float* Ab = AT ? (A + hk0 * lda) : (A + hk0);
    const float* Bb = B + hk0 * ldb;
    float* Cb = Cp + (long long)z * DIM * DIM;

    int m0 = blockIdx.y * 64;
    int n0 = blockIdx.x * 64;
    int tid = threadIdx.x;
    int tx = tid & 15;
    int ty = tid >> 4;

    float acc[4][4];
    #pragma unroll
    for (int i = 0; i < 4; i++)
        #pragma unroll
        for (int j = 0; j < 4; j++) acc[i][j] = 0.f;

    for (int k0 = 0; k0 < KS; k0 += 16) {
        if (AT) {
            int kk  = tid >> 4;
            int mm4 = (tid & 15) << 2;
            float4 a = *(const float4*)(Ab + (long long)(k0 + kk) * lda + m0 + mm4);
            *(float4*)&As[kk][mm4] = a;
        } else {
            int mm = tid >> 2;
            int kq = (tid & 3) << 2;
            float4 a = *(const float4*)(Ab + (long long)(m0 + mm) * lda + k0 + kq);
            As[kq + 0][mm] = a.x;
            As[kq + 1][mm] = a.y;
            As[kq + 2][mm] = a.z;
            As[kq + 3][mm] = a.w;
        }
        {
            int kk  = tid >> 4;
            int nn4 = (tid & 15) << 2;
            float4 b = *(const float4*)(Bb + (long long)(k0 + kk) * ldb + n0 + nn4);
            *(float4*)&Bs[kk][nn4] = b;
        }
        __syncthreads();

        #pragma unroll
        for (int kk = 0; kk < 16; kk++) {
            float ra[4], rb[4];
            #pragma unroll
            for (int i = 0; i < 4; i++) ra[i] = As[kk][ty * 4 + i];
            #pragma unroll
            for (int j = 0; j < 4; j++) rb[j] = Bs[kk][tx * 4 + j];
            #pragma unroll
            for (int i = 0; i < 4; i++)
                #pragma unroll
                for (int j = 0; j < 4; j++)
                    acc[i][j] = fmaf(ra[i], rb[j], acc[i][j]);
        }
        __syncthreads();
    }

    #pragma unroll
    for (int i = 0; i < 4; i++)
        #pragma unroll
        for (int j = 0; j < 4; j++)
            Cb[(long long)(m0 + ty * 4 + i) * DIM + (n0 + tx * 4 + j)] = acc[i][j];
}

// ------------- reduce split-K partials -> bf16 hi/lo ------------------------
__global__ void reduce_split_kernel(const float* __restrict__ part,
                                    __nv_bfloat16* __restrict__ hi,
                                    __nv_bfloat16* __restrict__ lo)
{
    int idx = blockIdx.x * 256 + threadIdx.x;    // over HEADS*DIM*DIM
    int h   = idx >> 16;
    int off = idx & 65535;
    const float* p = part + (long long)h * NSPLIT * 65536 + off;
    float acc = 0.f;
    #pragma unroll
    for (int s = 0; s < NSPLIT; s++) acc += p[(long long)s * 65536];
    __nv_bfloat16 hv = __float2bfloat16(acc);
    hi[idx] = hv;
    lo[idx] = __float2bfloat16(acc - __bfloat162float(hv));
}

// ---------------- bf16 split tensor-core GEMM (NT), reg-prefetch pipeline ---
#define LDSB 40
__device__ __forceinline__ void ldsm4(uint32_t* d, const __nv_bfloat16* p)
{
    uint32_t a = (uint32_t)__cvta_generic_to_shared(p);
    asm volatile("ldmatrix.sync.aligned.m8n8.x4.shared.b16 {%0,%1,%2,%3}, [%4];"
                 : "=r"(d[0]), "=r"(d[1]), "=r"(d[2]), "=r"(d[3]) : "r"(a));
}
__device__ __forceinline__ void mma16816(float* d, const uint32_t* a, const uint32_t* b)
{
    asm volatile(
        "mma.sync.aligned.m16n8k16.row.col.f32.bf16.bf16.f32 "
        "{%0,%1,%2,%3}, {%4,%5,%6,%7}, {%8,%9}, {%0,%1,%2,%3};"
        : "+f"(d[0]), "+f"(d[1]), "+f"(d[2]), "+f"(d[3])
        : "r"(a[0]), "r"(a[1]), "r"(a[2]), "r"(a[3]), "r"(b[0]), "r"(b[1]));
}

__global__ void __launch_bounds__(256)
mma_nt(const __nv_bfloat16* __restrict__ Ahi, const __nv_bfloat16* __restrict__ Alo,
       const __nv_bfloat16* __restrict__ Bhi, const __nv_bfloat16* __restrict__ Blo,
       float* __restrict__ C,
       int K, int lda, int ldb, int ldc,
       int hdiv,
       long long sAb, long long sAh,
       long long sBb, long long sBh,
       long long sCb, long long sCh,
       float alpha)
{
    __shared__ __align__(16) __nv_bfloat16 Ash[128][LDSB];
    __shared__ __align__(16) __nv_bfloat16 Asl[128][LDSB];
    __shared__ __align__(16) __nv_bfloat16 Bsh[128][LDSB];
    __shared__ __align__(16) __nv_bfloat16 Bsl[128][LDSB];

    int bz = blockIdx.z;
    int zb = bz / hdiv, zh = bz % hdiv;
    long long aoff = (long long)zb * sAb + (long long)zh * sAh;
    long long boff = (long long)zb * sBb + (long long)zh * sBh;
    float* Cb = C + (long long)zb * sCb + (long long)zh * sCh;

    int m0 = blockIdx.y * 128;
    int n0 = blockIdx.x * 128;
    int tid  = threadIdx.x;
    int warp = tid >> 5;
    int lane = tid & 31;
    int wm = (warp & 3) * 32;
    int wn = (warp >> 2) * 64;

    int r  = tid >> 2;            // 0..63
    int kc = (tid & 3) * 8;       // 0,8,16,24

    // global base pointers for this thread's two rows of each tile
    const __nv_bfloat16* pAh0 = Ahi + aoff + (long long)(m0 + r) * lda + kc;
    const __nv_bfloat16* pAl0 = Alo + aoff + (long long)(m0 + r) * lda + kc;
    const __nv_bfloat16* pBh0 = Bhi + boff + (long long)(n0 + r) * ldb + kc;
    const __nv_bfloat16* pBl0 = Blo + boff + (long long)(n0 + r) * ldb + kc;
    long long a64 = (long long)64 * lda;
    long long b64 = (long long)64 * ldb;

    float acc[2][8][4];
    #pragma unroll
    for (int i = 0; i < 2; i++)
        #pragma unroll
        for (int j = 0; j < 8; j++)
            #pragma unroll
            for (int c = 0; c < 4; c++) acc[i][j][c] = 0.f;

    // prefetch chunk 0 into registers
    uint4 fa_h[2], fa_l[2], fb_h[2], fb_l[2];
    #pragma unroll
    for (int i = 0; i < 2; i++) {
        fa_h[i] = *(const uint4*)(pAh0 + i * a64);
        fa_l[i] = *(const uint4*)(pAl0 + i * a64);
        fb_h[i] = *(const uint4*)(pBh0 + i * b64);
        fb_l[i] = *(const uint4*)(pBl0 + i * b64);
    }

    for (int k0 = 0; k0 < K; k0 += 32) {
        // commit current chunk to smem
        #pragma unroll
        for (int i = 0; i < 2; i++) {
            int row = r + i * 64;
            *(uint4*)&Ash[row][kc] = fa_h[i];
            *(uint4*)&Asl[row][kc] = fa_l[i];
            *(uint4*)&Bsh[row][kc] = fb_h[i];
            *(uint4*)&Bsl[row][kc] = fb_l[i];
        }
        __syncthreads();

        // issue next chunk's loads (latency overlapped with MMAs below)
        if (k0 + 32 < K) {
            long long d = k0 + 32;
            #pragma unroll
            for (int i = 0; i < 2; i++) {
                fa_h[i] = *(const uint4*)(pAh0 + i * a64 + d);
                fa_l[i] = *(const uint4*)(pAl0 + i * a64 + d);
                fb_h[i] = *(const uint4*)(pBh0 + i * b64 + d);
                fb_l[i] = *(const uint4*)(pBl0 + i * b64 + d);
            }
        }

        #pragma unroll
        for (int s = 0; s < 32; s += 16) {
            uint32_t ah[2][4], al[2][4];
            #pragma unroll
            for (int i = 0; i < 2; i++) {
                int row = wm + i * 16 + (lane & 15);
                int col = s + ((lane >> 4) << 3);
                ldsm4(ah[i], &Ash[row][col]);
                ldsm4(al[i], &Asl[row][col]);
            }
            #pragma unroll
            for (int j = 0; j < 4; j++) {
                int row = wn + j * 16 + ((lane >> 4) << 3) + (lane & 7);
                int col = s + ((lane >> 3) & 1) * 8;
                uint32_t bh[4], bl[4];
                ldsm4(bh, &Bsh[row][col]);
                ldsm4(bl, &Bsl[row][col]);
                #pragma unroll
                for (int jj = 0; jj < 2; jj++) {
                    #pragma unroll
                    for (int i = 0; i < 2; i++) {
                        mma16816(acc[i][j * 2 + jj], ah[i], bh + jj * 2);
                        mma16816(acc[i][j * 2 + jj], ah[i], bl + jj * 2);
                        mma16816(acc[i][j * 2 + jj], al[i], bh + jj * 2);
                    }
                }
            }
        }
        __syncthreads();
    }

    #pragma unroll
    for (int i = 0; i < 2; i++) {
        #pragma unroll
        for (int j = 0; j < 8; j++) {
            int row = m0 + wm + i * 16 + (lane >> 2);
            int col = n0 + wn + j * 8 + (lane & 3) * 2;
            float2 v0 = { alpha * acc[i][j][0], alpha * acc[i][j][1] };
            float2 v1 = { alpha * acc[i][j][2], alpha * acc[i][j][3] };
            *(float2*)(Cb + (long long)row * ldc + col)       = v0;
            *(float2*)(Cb + (long long)(row + 8) * ldc + col) = v1;
        }
    }
}

// ---------------- row softmax (2048 cols) + bf16 hi/lo split ----------------
__global__ void softmax_split_kernel(const float* __restrict__ S,
                                     __nv_bfloat16* __restrict__ Phi,
                                     __nv_bfloat16* __restrict__ Plo)
{
    size_t row = blockIdx.x;
    const float* sr = S + row * (size_t)NTOK;
    int t = threadIdx.x;

    float v[8];
    float m = -1e30f;
    #pragma unroll
    for (int i = 0; i < 8; i++) {
        v[i] = sr[t + 256 * i];
        m = fmaxf(m, v[i]);
    }

    __shared__ float sred[8];
    float w = m;
    #pragma unroll
    for (int o = 16; o > 0; o >>= 1) w = fmaxf(w, __shfl_xor_sync(0xffffffffu, w, o));
    if ((t & 31) == 0) sred[t >> 5] = w;
    __syncthreads();
    if (t == 0) {
        float z = sred[0];
        #pragma unroll
        for (int i = 1; i < 8; i++) z = fmaxf(z, sred[i]);
        sred[0] = z;
    }
    __syncthreads();
    m = sred[0];
    __syncthreads();

    float sum = 0.f;
    #pragma unroll
    for (int i = 0; i < 8; i++) {
        v[i] = __expf(v[i] - m);
        sum += v[i];
    }
    float w2 = sum;
    #pragma unroll
    for (int o = 16; o > 0; o >>= 1) w2 += __shfl_xor_sync(0xffffffffu, w2, o);
    if ((t & 31) == 0) sred[t >> 5] = w2;
    __syncthreads();
    if (t == 0) {
        float z = 0.f;
        #pragma unroll
        for (int i = 0; i < 8; i++) z += sred[i];
        sred[0] = z;
    }
    __syncthreads();
    float inv = 1.0f / sred[0];

    size_t base = row * (size_t)NTOK;
    #pragma unroll
    for (int i = 0; i < 8; i++) {
        float p = v[i] * inv;
        __nv_bfloat16 h = __float2bfloat16(p);
        Phi[base + t + 256 * i] = h;
        Plo[base + t + 256 * i] = __float2bfloat16(p - __bfloat162float(h));
    }
}

// ---------------- reduce per-head partials ----------------------------------
__global__ void reduce_kernel(const float* __restrict__ op, float* __restrict__ out)
{
    int row = blockIdx.x;
    int t   = threadIdx.x;
    int b   = row >> 11;
    int q   = row & 2047;
    const float* base = op + (((long long)b * HEADS) * NTOK + q) * DIM + t;
    float acc = 0.f;
    #pragma unroll
    for (int h = 0; h < HEADS; h++)
        acc += base[(long long)h * NTOK * DIM];
    out[(long long)row * DIM + t] = acc;
}

// ---------------- launch ----------------------------------------------------
extern "C" void kernel_launch(void* const* d_in, const int* in_sizes, int n_in,
                              void* d_out, int out_size)
{
    const float* x     = (const float*)d_in[0];
    const float* gamma = (const float*)d_in[1];
    const float* Wq    = (const float*)d_in[2];
    const float* Wk    = (const float*)d_in[3];
    const float* Wv    = (const float*)d_in[4];
    const float* Wo    = (const float*)d_in[5];
    float* out = (float*)d_out;

    float *xn, *pm, *pg, *tt, *ut, *s, *op;
    __nv_bfloat16 *xnh, *xnl, *mth, *mtl, *ghh, *ghl, *th, *tl, *uth, *utl, *ph, *pl;
    cudaGetSymbolAddress((void**)&xn,  g_xn);
    cudaGetSymbolAddress((void**)&pm,  g_pm);
    cudaGetSymbolAddress((void**)&pg,  g_pg);
    cudaGetSymbolAddress((void**)&tt,  g_t);
    cudaGetSymbolAddress((void**)&ut,  g_ut);
    cudaGetSymbolAddress((void**)&s,   g_s);
    cudaGetSymbolAddress((void**)&op,  g_op);
    cudaGetSymbolAddress((void**)&xnh, g_xnh);
    cudaGetSymbolAddress((void**)&xnl, g_xnl);
    cudaGetSymbolAddress((void**)&mth, g_mth);
    cudaGetSymbolAddress((void**)&mtl, g_mtl);
    cudaGetSymbolAddress((void**)&ghh, g_gh_);
    cudaGetSymbolAddress((void**)&ghl, g_gl_);
    cudaGetSymbolAddress((void**)&th,  g_th);
    cudaGetSymbolAddress((void**)&tl,  g_tl);
    cudaGetSymbolAddress((void**)&uth, g_uth);
    cudaGetSymbolAddress((void**)&utl, g_utl);
    cudaGetSymbolAddress((void**)&ph,  g_ph);
    cudaGetSymbolAddress((void**)&pl,  g_pl);

    const long long TD  = (long long)NTOK * DIM;
    const long long HTD = (long long)HEADS * TD;
    const long long SB  = (long long)NTOK * INNER;
    const long long DD  = (long long)DIM * DIM;

    // 1) LayerNorm + split (precomputes below don't depend on it; stream order is fine)
    ln_kernel<<<TOK, 256>>>(x, gamma, xn);
    split_kernel<<<(TOK * DIM / 4 + 255) / 256, 256>>>(xn, xnh, xnl, TOK * DIM / 4);

    // 2) precomputes, split-K:
    //    Mt_h = Wk_h^T * Wq_h  (so T = NT(xn, Mt));  G_h = Wo_h * Wv_h
    {
        dim3 grid(4, 4, HEADS * NSPLIT);
        gemm64_sk<true ><<<grid, 256>>>(Wk, Wq, pm, DIM, DIM);
        gemm64_sk<false><<<grid, 256>>>(Wo, Wv, pg, INNER, DIM);
        reduce_split_kernel<<<HEADS * DIM * DIM / 256, 256>>>(pm, mth, mtl);
        reduce_split_kernel<<<HEADS * DIM * DIM / 256, 256>>>(pg, ghh, ghl);
    }

    // 3) T[b][h] = xn_b * Mt_h^T  (tensor cores, NT), then split
    {
        dim3 grid(DIM / 128, NTOK / 128, BATCH * HEADS);
        mma_nt<<<grid, 256>>>(
            xnh, xnl, mth, mtl, tt,
            DIM, DIM, DIM, DIM, HEADS,
            TD, 0,
            0, DD,
            HTD, TD,
            1.0f);
    }
    split_kernel<<<(int)((BATCH * HTD / 4 + 255) / 256), 256>>>(tt, th, tl, BATCH * HTD / 4);

    // 4) S = scale * T * xn^T  (tensor cores, NT)
    {
        dim3 grid(NTOK / 128, NTOK / 128, BATCH * HEADS);
        mma_nt<<<grid, 256>>>(
            th, tl, xnh, xnl, s,
            DIM, DIM, DIM, INNER, HEADS,
            HTD, TD,
            TD, 0,
            SB, (long long)DHEAD,
            ATT_SCALE);
    }

    // 5) softmax + P split
    softmax_split_kernel<<<BATCH * NTOK * HEADS, 256>>>(s, ph, pl);

    // 6) Ut[b][h] = G_h * xn_b^T  (tensor cores, NT: A=G (DIMxDIM), B=xn), then split
    {
        dim3 grid(NTOK / 128, DIM / 128, BATCH * HEADS);
        mma_nt<<<grid, 256>>>(
            ghh, ghl, xnh, xnl, ut,
            DIM, DIM, DIM, NTOK, HEADS,
            0, DD,
            TD, 0,
            HTD, TD,
            1.0f);
    }
    split_kernel<<<(int)((BATCH * HTD / 4 + 255) / 256), 256>>>(ut, uth, utl, BATCH * HTD / 4);

    // 7) op[b][h] = P[b][h] * Ut[b][h]^T  (tensor cores, NT)
    {
        dim3 grid(DIM / 128, NTOK / 128, BATCH * HEADS);
        mma_nt<<<grid, 256>>>(
            ph, pl, uth, utl, op,
            NTOK, INNER, NTOK, DIM, HEADS,
            SB, (long long)DHEAD,
            HTD, TD,
            HTD, TD,
            1.0f);
    }

    // 8) out = sum_h op[b][h]
    reduce_kernel<<<TOK, 256>>>(op, out);
}